// round 2
// baseline (speedup 1.0000x reference)
#include <cuda_runtime.h>

// mLSTM cell, B=32768, H=512, fp32 end-to-end.
// Kernel 1: m = x@W_m + h@U_m + b_m ; x_tilde = x * m  -> scratch
// Kernel 2: 4 gate pre-activations (8 GEMMs, shared A tiles) + fused cell update -> h_t

#define BDIM 32768
#define HDIM 512

// 64 MB scratch for x_tilde (allocation-free: __device__ global)
__device__ float g_xtilde[(size_t)BDIM * HDIM];

// ---- packed f32x2 helpers (FFMA2: 2 fp32 FMAs per instruction) ----
__device__ __forceinline__ unsigned long long pack2(float v) {
    unsigned long long r;
    asm("mov.b64 %0, {%1, %1};" : "=l"(r) : "f"(v));
    return r;
}
__device__ __forceinline__ void fma2(unsigned long long& d,
                                     unsigned long long a,
                                     unsigned long long b) {
    asm("fma.rn.f32x2 %0, %1, %2, %0;" : "+l"(d) : "l"(a), "l"(b));
}
__device__ __forceinline__ float2 unpack2(unsigned long long v) {
    float2 f;
    asm("mov.b64 {%0, %1}, %2;" : "=f"(f.x), "=f"(f.y) : "l"(v));
    return f;
}

__device__ __forceinline__ float sigmoidf_fast(float z) {
    return 1.0f / (1.0f + __expf(-z));
}

// ============================================================================
// Kernel 1: m-gate GEMM + x_tilde epilogue
// Tile: 64x64 per CTA, 256 threads, each thread 4x4 outputs, K-chunk = 16
// ============================================================================
__global__ __launch_bounds__(256) void k_mgate(
    const float* __restrict__ x, const float* __restrict__ h,
    const float* __restrict__ Wm, const float* __restrict__ Um,
    const float* __restrict__ bm)
{
    __shared__ float As_x[16][64];
    __shared__ float As_h[16][64];
    __shared__ float Bs_w[16][64];
    __shared__ float Bs_u[16][64];

    const int n0 = blockIdx.x * 64;
    const int m0 = blockIdx.y * 64;
    const int tid = threadIdx.x;
    const int tm = tid >> 4;          // 0..15
    const int tn = tid & 15;          // 0..15

    // global->smem load mapping
    const int lm = tid >> 2;          // 0..63 (A rows)
    const int lk = (tid & 3) * 4;     // 0,4,8,12 (A cols, float4)
    const int bk = tid >> 4;          // 0..15 (B rows)
    const int bn = (tid & 15) * 4;    // B cols, float4

    unsigned long long acc[4][2];
#pragma unroll
    for (int i = 0; i < 4; i++)
#pragma unroll
        for (int j = 0; j < 2; j++) acc[i][j] = 0ull;

    const size_t arow = (size_t)(m0 + lm) * HDIM;

    for (int k0 = 0; k0 < HDIM; k0 += 16) {
        float4 gx = *(const float4*)&x[arow + k0 + lk];
        float4 gh = *(const float4*)&h[arow + k0 + lk];
        float4 gw = *(const float4*)&Wm[(size_t)(k0 + bk) * HDIM + n0 + bn];
        float4 gu = *(const float4*)&Um[(size_t)(k0 + bk) * HDIM + n0 + bn];
        __syncthreads();
        As_x[lk + 0][lm] = gx.x; As_x[lk + 1][lm] = gx.y;
        As_x[lk + 2][lm] = gx.z; As_x[lk + 3][lm] = gx.w;
        As_h[lk + 0][lm] = gh.x; As_h[lk + 1][lm] = gh.y;
        As_h[lk + 2][lm] = gh.z; As_h[lk + 3][lm] = gh.w;
        *(float4*)&Bs_w[bk][bn] = gw;
        *(float4*)&Bs_u[bk][bn] = gu;
        __syncthreads();

#pragma unroll
        for (int kk = 0; kk < 16; kk++) {
            float4 ax = *(const float4*)&As_x[kk][tm * 4];
            float4 ah = *(const float4*)&As_h[kk][tm * 4];
            ulonglong2 bw = *(const ulonglong2*)&Bs_w[kk][tn * 4];
            ulonglong2 bu = *(const ulonglong2*)&Bs_u[kk][tn * 4];
            unsigned long long apx[4] = {pack2(ax.x), pack2(ax.y), pack2(ax.z), pack2(ax.w)};
            unsigned long long aph[4] = {pack2(ah.x), pack2(ah.y), pack2(ah.z), pack2(ah.w)};
#pragma unroll
            for (int i = 0; i < 4; i++) {
                fma2(acc[i][0], apx[i], bw.x);
                fma2(acc[i][1], apx[i], bw.y);
                fma2(acc[i][0], aph[i], bu.x);
                fma2(acc[i][1], aph[i], bu.y);
            }
        }
    }

    // epilogue: x_tilde = x * (m + b_m)
#pragma unroll
    for (int i = 0; i < 4; i++) {
        const int m = m0 + tm * 4 + i;
        const size_t rbase = (size_t)m * HDIM;
#pragma unroll
        for (int j2 = 0; j2 < 2; j2++) {
            float2 v = unpack2(acc[i][j2]);
            const int n = n0 + tn * 4 + j2 * 2;
            float2 xv = *(const float2*)&x[rbase + n];
            float2 r;
            r.x = xv.x * (v.x + bm[n]);
            r.y = xv.y * (v.y + bm[n + 1]);
            *(float2*)&g_xtilde[rbase + n] = r;
        }
    }
}

// ============================================================================
// Kernel 2: 4 gates (8 GEMMs fused) + cell update -> h_t
// Gate order: 0=i (A: x_tilde), 1=f, 2=o, 3=c (A: x); all use h for U-part
// ============================================================================
__global__ __launch_bounds__(256) void k_gates(
    const float* __restrict__ x, const float* __restrict__ h,
    const float* __restrict__ c_prev,
    const float* __restrict__ Wi, const float* __restrict__ Ui,
    const float* __restrict__ Wf, const float* __restrict__ Uf,
    const float* __restrict__ Wo, const float* __restrict__ Uo,
    const float* __restrict__ Wc, const float* __restrict__ Uc,
    const float* __restrict__ bi, const float* __restrict__ bf,
    const float* __restrict__ bo, const float* __restrict__ bc,
    float* __restrict__ out)
{
    __shared__ float As_x[16][64];
    __shared__ float As_t[16][64];
    __shared__ float As_h[16][64];
    __shared__ float Bs[8][16][64];   // Wi,Ui,Wf,Uf,Wo,Uo,Wc,Uc

    const int n0 = blockIdx.x * 64;
    const int m0 = blockIdx.y * 64;
    const int tid = threadIdx.x;
    const int tm = tid >> 4;
    const int tn = tid & 15;

    const int lm = tid >> 2;
    const int lk = (tid & 3) * 4;
    const int bk = tid >> 4;
    const int bn = (tid & 15) * 4;

    const float* Ws[8] = {Wi, Ui, Wf, Uf, Wo, Uo, Wc, Uc};

    unsigned long long acc[4][4][2];  // [gate][i][j2]
#pragma unroll
    for (int g = 0; g < 4; g++)
#pragma unroll
        for (int i = 0; i < 4; i++)
#pragma unroll
            for (int j = 0; j < 2; j++) acc[g][i][j] = 0ull;

    const size_t arow = (size_t)(m0 + lm) * HDIM;

    for (int k0 = 0; k0 < HDIM; k0 += 16) {
        float4 gx = *(const float4*)&x[arow + k0 + lk];
        float4 gt = *(const float4*)&g_xtilde[arow + k0 + lk];
        float4 gh = *(const float4*)&h[arow + k0 + lk];
        float4 gb[8];
#pragma unroll
        for (int w = 0; w < 8; w++)
            gb[w] = *(const float4*)&Ws[w][(size_t)(k0 + bk) * HDIM + n0 + bn];

        __syncthreads();
        As_x[lk + 0][lm] = gx.x; As_x[lk + 1][lm] = gx.y;
        As_x[lk + 2][lm] = gx.z; As_x[lk + 3][lm] = gx.w;
        As_t[lk + 0][lm] = gt.x; As_t[lk + 1][lm] = gt.y;
        As_t[lk + 2][lm] = gt.z; As_t[lk + 3][lm] = gt.w;
        As_h[lk + 0][lm] = gh.x; As_h[lk + 1][lm] = gh.y;
        As_h[lk + 2][lm] = gh.z; As_h[lk + 3][lm] = gh.w;
#pragma unroll
        for (int w = 0; w < 8; w++)
            *(float4*)&Bs[w][bk][bn] = gb[w];
        __syncthreads();

#pragma unroll
        for (int kk = 0; kk < 16; kk++) {
            float4 ax = *(const float4*)&As_x[kk][tm * 4];
            float4 at = *(const float4*)&As_t[kk][tm * 4];
            float4 ah = *(const float4*)&As_h[kk][tm * 4];
            unsigned long long apx[4] = {pack2(ax.x), pack2(ax.y), pack2(ax.z), pack2(ax.w)};
            unsigned long long apt[4] = {pack2(at.x), pack2(at.y), pack2(at.z), pack2(at.w)};
            unsigned long long aph[4] = {pack2(ah.x), pack2(ah.y), pack2(ah.z), pack2(ah.w)};
#pragma unroll
            for (int g = 0; g < 4; g++) {
                ulonglong2 bw = *(const ulonglong2*)&Bs[2 * g][kk][tn * 4];
                ulonglong2 bu = *(const ulonglong2*)&Bs[2 * g + 1][kk][tn * 4];
#pragma unroll
                for (int i = 0; i < 4; i++) {
                    unsigned long long a0 = (g == 0) ? apt[i] : apx[i];
                    fma2(acc[g][i][0], a0, bw.x);
                    fma2(acc[g][i][1], a0, bw.y);
                    fma2(acc[g][i][0], aph[i], bu.x);
                    fma2(acc[g][i][1], aph[i], bu.y);
                }
            }
        }
    }

    // fused cell-update epilogue
#pragma unroll
    for (int i = 0; i < 4; i++) {
        const int m = m0 + tm * 4 + i;
        const size_t rbase = (size_t)m * HDIM;
#pragma unroll
        for (int j2 = 0; j2 < 2; j2++) {
            const int n = n0 + tn * 4 + j2 * 2;
            float2 vi = unpack2(acc[0][i][j2]);
            float2 vf = unpack2(acc[1][i][j2]);
            float2 vo = unpack2(acc[2][i][j2]);
            float2 vc = unpack2(acc[3][i][j2]);
            float2 cp = *(const float2*)&c_prev[rbase + n];
            float2 r;
            {
                float ig = sigmoidf_fast(vi.x + bi[n]);
                float fg = sigmoidf_fast(vf.x + bf[n]);
                float og = sigmoidf_fast(vo.x + bo[n]);
                float ct = tanhf(vc.x + bc[n]);
                float cc = fg * cp.x + ig * ct;
                r.x = og * tanhf(cc);
            }
            {
                float ig = sigmoidf_fast(vi.y + bi[n + 1]);
                float fg = sigmoidf_fast(vf.y + bf[n + 1]);
                float og = sigmoidf_fast(vo.y + bo[n + 1]);
                float ct = tanhf(vc.y + bc[n + 1]);
                float cc = fg * cp.y + ig * ct;
                r.y = og * tanhf(cc);
            }
            *(float2*)&out[rbase + n] = r;
        }
    }
}

// ============================================================================
extern "C" void kernel_launch(void* const* d_in, const int* in_sizes, int n_in,
                              void* d_out, int out_size) {
    const float* x  = (const float*)d_in[0];
    const float* h  = (const float*)d_in[1];
    const float* c  = (const float*)d_in[2];
    const float* Wm = (const float*)d_in[3];
    const float* Um = (const float*)d_in[4];
    const float* Wi = (const float*)d_in[5];
    const float* Ui = (const float*)d_in[6];
    const float* Wf = (const float*)d_in[7];
    const float* Uf = (const float*)d_in[8];
    const float* Wo = (const float*)d_in[9];
    const float* Uo = (const float*)d_in[10];
    const float* Wc = (const float*)d_in[11];
    const float* Uc = (const float*)d_in[12];
    const float* bm = (const float*)d_in[13];
    const float* bi = (const float*)d_in[14];
    const float* bf = (const float*)d_in[15];
    const float* bo = (const float*)d_in[16];
    const float* bc = (const float*)d_in[17];
    float* out = (float*)d_out;

    dim3 grid(HDIM / 64, BDIM / 64);
    dim3 block(256);
    k_mgate<<<grid, block>>>(x, h, Wm, Um, bm);
    k_gates<<<grid, block>>>(x, h, c, Wi, Ui, Wf, Uf, Wo, Uo, Wc, Uc,
                             bi, bf, bo, bc, out);
}

// round 4
// speedup vs baseline: 6.1901x; 6.1901x over previous
#include <cuda_runtime.h>
#include <cuda_fp16.h>
#include <cstdint>
#include <cstddef>

#define BDIM 32768
#define HDIM 512
#define KCAT 1024
#define GW ((size_t)HDIM * KCAT)
#define NCHUNK 16           /* K=1024 / 64 */
#define STAGE 32768u        /* 16KB A + 16KB B per stage */
#define DSMEM (2 * 32768)

typedef __half h16;

// persistent scratch (allocation-free)
__device__ h16 g_xf[(size_t)BDIM * HDIM];
__device__ h16 g_hf[(size_t)BDIM * HDIM];
__device__ h16 g_tf[(size_t)BDIM * HDIM];
__device__ h16 g_W[5 * GW];                 // [gate][n][kcat], gates: 0=m 1=i 2=f 3=o 4=c
__device__ float g_ft[(size_t)BDIM * HDIM];
__device__ float g_ot[(size_t)BDIM * HDIM];
__device__ float g_ct[(size_t)BDIM * HDIM];

__device__ __forceinline__ uint32_t smem_u32(const void* p) {
    uint32_t a;
    asm("{ .reg .u64 t; cvta.to.shared.u64 t, %1; cvt.u32.u64 %0, t; }" : "=r"(a) : "l"(p));
    return a;
}
__device__ __forceinline__ void cpa16(uint32_t dst, const void* src) {
    asm volatile("cp.async.cg.shared.global [%0], [%1], 16;" :: "r"(dst), "l"(src) : "memory");
}
__device__ __forceinline__ void ldmx4(uint32_t* d, uint32_t addr) {
    asm volatile("ldmatrix.sync.aligned.m8n8.x4.shared.b16 {%0,%1,%2,%3}, [%4];"
                 : "=r"(d[0]), "=r"(d[1]), "=r"(d[2]), "=r"(d[3]) : "r"(addr));
}
__device__ __forceinline__ void mma16816(float* c, const uint32_t* a, uint32_t b0, uint32_t b1) {
    asm volatile(
        "mma.sync.aligned.m16n8k16.row.col.f32.f16.f16.f32 "
        "{%0,%1,%2,%3}, {%4,%5,%6,%7}, {%8,%9}, {%0,%1,%2,%3};"
        : "+f"(c[0]), "+f"(c[1]), "+f"(c[2]), "+f"(c[3])
        : "r"(a[0]), "r"(a[1]), "r"(a[2]), "r"(a[3]), "r"(b0), "r"(b1));
}
__device__ __forceinline__ uint32_t swz(uint32_t off) { return off ^ ((off >> 3) & 0x70u); }
__device__ __forceinline__ float sigf(float z) { return 1.0f / (1.0f + __expf(-z)); }

// ---------------- prep ----------------
__global__ void prep_half(const float* __restrict__ s, h16* __restrict__ d, int n4) {
    const float4* s4 = (const float4*)s;
    uint32_t* d2 = (uint32_t*)d;
    int stride = gridDim.x * blockDim.x;
    for (int i = blockIdx.x * blockDim.x + threadIdx.x; i < n4; i += stride) {
        float4 v = s4[i];
        __half2 p0 = __floats2half2_rn(v.x, v.y);
        __half2 p1 = __floats2half2_rn(v.z, v.w);
        d2[2 * i] = *(uint32_t*)&p0;
        d2[2 * i + 1] = *(uint32_t*)&p1;
    }
}

// transpose W[k][n] (10 mats) -> g_W[gate][n][kh*512+k] fp16
__global__ void prep_wt(const float* __restrict__ p0, const float* __restrict__ p1,
                        const float* __restrict__ p2, const float* __restrict__ p3,
                        const float* __restrict__ p4, const float* __restrict__ p5,
                        const float* __restrict__ p6, const float* __restrict__ p7,
                        const float* __restrict__ p8, const float* __restrict__ p9,
                        h16* __restrict__ W) {
    const float* mats[10] = {p0, p1, p2, p3, p4, p5, p6, p7, p8, p9};
    const float* src = mats[blockIdx.z];
    const int g = blockIdx.z >> 1, kh = blockIdx.z & 1;
    __shared__ float t[32][33];
    const int tx = threadIdx.x & 31, ty = threadIdx.x >> 5;
    const int k0 = blockIdx.x * 32, n0 = blockIdx.y * 32;
#pragma unroll
    for (int i = 0; i < 4; ++i)
        t[ty + i * 8][tx] = src[(size_t)(k0 + ty + i * 8) * HDIM + n0 + tx];
    __syncthreads();
#pragma unroll
    for (int i = 0; i < 4; ++i) {
        int r = ty + i * 8;
        W[(size_t)g * GW + (size_t)(n0 + r) * KCAT + kh * HDIM + k0 + tx] =
            __float2half_rn(t[tx][r]);
    }
}

// ---------------- main GEMM ----------------
// MODE 0: m-gate -> tf = fp16(x * (acc + bias))          (aux0 = x)
// MODE 1: sigmoid (z<2) / tanh (z==2) -> outz fp32
// MODE 3: i-gate: h_t = o * tanh(f*c_prev + sig(acc+b)*c_tilde)
//         (aux0=c_prev, aux1=f_t, aux2=o_t, aux3=c_tilde) -> o0
template <int MODE>
__global__ void __launch_bounds__(256, 2) k_mma(
    const h16* __restrict__ A1, const h16* __restrict__ A2,
    const h16* __restrict__ Wall, int gate0,
    const float* __restrict__ b0, const float* __restrict__ b1,
    const float* __restrict__ b2,
    float* __restrict__ o0, float* __restrict__ o1, float* __restrict__ o2,
    const float* __restrict__ aux0, const float* __restrict__ aux1,
    const float* __restrict__ aux2, const float* __restrict__ aux3,
    h16* __restrict__ tfo)
{
    extern __shared__ char sm[];
    const int tid = threadIdx.x, lane = tid & 31, wid = tid >> 5;
    const int wm = wid & 3, wn = wid >> 2;
    const int m0 = blockIdx.y * 128, n0 = blockIdx.x * 128;
    const int z = blockIdx.z;
    const h16* W = Wall + (size_t)(gate0 + z) * GW;
    const float* bias = (z == 0) ? b0 : (z == 1) ? b1 : b2;
    float* outp = (z == 0) ? o0 : (z == 1) ? o1 : o2;

    const uint32_t sbase = smem_u32(sm);
    const int fr = tid >> 3, fsg = tid & 7;   // fill row / 16B-seg

    float acc[2][8][4];
#pragma unroll
    for (int a = 0; a < 2; ++a)
#pragma unroll
        for (int b = 0; b < 8; ++b)
#pragma unroll
            for (int c = 0; c < 4; ++c) acc[a][b][c] = 0.f;

    auto fill = [&](int c) {
        const uint32_t st = sbase + (uint32_t)(c & 1) * STAGE;
        const int kcat = c * 64;
        const h16* Ap = (kcat < HDIM) ? A1 : A2;
        const int kloc = kcat & (HDIM - 1);
#pragma unroll
        for (int i = 0; i < 4; ++i) {
            int rr = fr + i * 32;
            uint32_t off = (uint32_t)(rr * 128 + fsg * 16);
            cpa16(st + swz(off), Ap + (size_t)(m0 + rr) * HDIM + kloc + fsg * 8);
        }
#pragma unroll
        for (int i = 0; i < 4; ++i) {
            int rr = fr + i * 32;
            uint32_t off = (uint32_t)(rr * 128 + fsg * 16);
            cpa16(st + 16384u + swz(off), W + (size_t)(n0 + rr) * KCAT + kcat + fsg * 8);
        }
        asm volatile("cp.async.commit_group;" ::: "memory");
    };

    fill(0);
    for (int c = 0; c < NCHUNK; ++c) {
        if (c + 1 < NCHUNK) {
            fill(c + 1);
            asm volatile("cp.async.wait_group 1;" ::: "memory");
        } else {
            asm volatile("cp.async.wait_group 0;" ::: "memory");
        }
        __syncthreads();

        const uint32_t sA = sbase + (uint32_t)(c & 1) * STAGE;
        const uint32_t sB = sA + 16384u;
#pragma unroll
        for (int ks = 0; ks < 4; ++ks) {
            uint32_t a[2][4];
#pragma unroll
            for (int mi = 0; mi < 2; ++mi) {
                uint32_t off = (uint32_t)((wm * 32 + mi * 16 + (lane & 15)) * 128 +
                                          ks * 32 + (lane >> 4) * 16);
                ldmx4(a[mi], sA + swz(off));
            }
#pragma unroll
            for (int ni = 0; ni < 4; ++ni) {
                uint32_t b[4];
                uint32_t off = (uint32_t)((wn * 64 + ni * 16 + (lane & 15)) * 128 +
                                          ks * 32 + (lane >> 4) * 16);
                ldmx4(b, sB + swz(off));
#pragma unroll
                for (int mi = 0; mi < 2; ++mi) {
                    mma16816(acc[mi][2 * ni],     a[mi], b[0], b[2]);
                    mma16816(acc[mi][2 * ni + 1], a[mi], b[1], b[3]);
                }
            }
        }
        __syncthreads();
    }

    // -------- epilogue --------
#pragma unroll
    for (int mi = 0; mi < 2; ++mi) {
        const int rbase = m0 + wm * 32 + mi * 16 + (lane >> 2);
#pragma unroll
        for (int nj = 0; nj < 8; ++nj) {
            const int col = n0 + wn * 64 + nj * 8 + (lane & 3) * 2;
            const float bx = bias[col], by = bias[col + 1];
#pragma unroll
            for (int half = 0; half < 2; ++half) {
                const int row = rbase + half * 8;
                const size_t idx = (size_t)row * HDIM + col;
                float v0 = acc[mi][nj][2 * half] + bx;
                float v1 = acc[mi][nj][2 * half + 1] + by;
                if (MODE == 0) {
                    float2 xv = *(const float2*)(aux0 + idx);
                    __half2 p = __floats2half2_rn(xv.x * v0, xv.y * v1);
                    *(uint32_t*)(tfo + idx) = *(uint32_t*)&p;
                } else if (MODE == 1) {
                    float2 o;
                    if (z < 2) { o.x = sigf(v0); o.y = sigf(v1); }
                    else       { o.x = tanhf(v0); o.y = tanhf(v1); }
                    *(float2*)(outp + idx) = o;
                } else {
                    float2 cp = *(const float2*)(aux0 + idx);
                    float2 ft = *(const float2*)(aux1 + idx);
                    float2 ot = *(const float2*)(aux2 + idx);
                    float2 ct = *(const float2*)(aux3 + idx);
                    float2 o;
                    o.x = ot.x * tanhf(ft.x * cp.x + sigf(v0) * ct.x);
                    o.y = ot.y * tanhf(ft.y * cp.y + sigf(v1) * ct.y);
                    *(float2*)(outp + idx) = o;
                }
            }
        }
    }
}

// ---------------- launch ----------------
extern "C" void kernel_launch(void* const* d_in, const int* in_sizes, int n_in,
                              void* d_out, int out_size) {
    const float* x = (const float*)d_in[0];
    const float* h = (const float*)d_in[1];
    const float* c = (const float*)d_in[2];
    const float* W10[10] = {(const float*)d_in[3],  (const float*)d_in[4],
                            (const float*)d_in[5],  (const float*)d_in[6],
                            (const float*)d_in[7],  (const float*)d_in[8],
                            (const float*)d_in[9],  (const float*)d_in[10],
                            (const float*)d_in[11], (const float*)d_in[12]};
    const float* bm = (const float*)d_in[13];
    const float* bi = (const float*)d_in[14];
    const float* bf = (const float*)d_in[15];
    const float* bo = (const float*)d_in[16];
    const float* bc = (const float*)d_in[17];
    float* out = (float*)d_out;

    cudaFuncSetAttribute(k_mma<0>, cudaFuncAttributeMaxDynamicSharedMemorySize, DSMEM);
    cudaFuncSetAttribute(k_mma<1>, cudaFuncAttributeMaxDynamicSharedMemorySize, DSMEM);
    cudaFuncSetAttribute(k_mma<3>, cudaFuncAttributeMaxDynamicSharedMemorySize, DSMEM);

    h16 *xf, *hf, *tf, *Wd;
    float *ft, *ot, *ct;
    cudaGetSymbolAddress((void**)&xf, g_xf);
    cudaGetSymbolAddress((void**)&hf, g_hf);
    cudaGetSymbolAddress((void**)&tf, g_tf);
    cudaGetSymbolAddress((void**)&Wd, g_W);
    cudaGetSymbolAddress((void**)&ft, g_ft);
    cudaGetSymbolAddress((void**)&ot, g_ot);
    cudaGetSymbolAddress((void**)&ct, g_ct);

    const int n4 = BDIM * HDIM / 4;
    prep_half<<<2048, 256>>>(x, xf, n4);
    prep_half<<<2048, 256>>>(h, hf, n4);
    prep_wt<<<dim3(16, 16, 10), 256>>>(W10[0], W10[1], W10[2], W10[3], W10[4],
                                       W10[5], W10[6], W10[7], W10[8], W10[9], Wd);

    dim3 g1(HDIM / 128, BDIM / 128, 1);
    dim3 g3(HDIM / 128, BDIM / 128, 3);
    // m-gate: writes tf = fp16(x * m_t)
    k_mma<0><<<g1, 256, DSMEM>>>(xf, hf, Wd, 0, bm, nullptr, nullptr,
                                 nullptr, nullptr, nullptr,
                                 x, nullptr, nullptr, nullptr, tf);
    // f, o, c gates fused in one launch (z selects gate)
    k_mma<1><<<g3, 256, DSMEM>>>(xf, hf, Wd, 2, bf, bo, bc,
                                 ft, ot, ct,
                                 nullptr, nullptr, nullptr, nullptr, nullptr);
    // i-gate + final cell update
    k_mma<3><<<g1, 256, DSMEM>>>(tf, hf, Wd, 1, bi, nullptr, nullptr,
                                 out, nullptr, nullptr,
                                 c, ft, ot, ct, nullptr);
}